// round 4
// baseline (speedup 1.0000x reference)
#include <cuda_runtime.h>
#include <math.h>

#define NK   16
#define DLAT 128
#define MM   100
#define NS   136
#define NB   8192
#define ROWS 32
#define THREADS 256
#define NGROUP 8           // THREADS / ROWS
#define SPG 17             // NS / NGROUP
#define ZSTRIDE 132        // row stride for z tile (float4-aligned, bank-skewed)

// ---------- device scratch ----------
__device__ float g_logpi[NS];
__device__ float g_bb[NS];      // |muB|^2
__device__ float g_cb[NS];      // muB . (muA - muB)
__device__ float g_u[NS * MM];  // exp(gamma_s * w_m^2)

// ---------- prep: block 0 = softmax(pi)+outputs; blocks 1..NS = per-state ----------
__global__ void k_prep(const float* __restrict__ pi, const float* __restrict__ mu,
                       const int* __restrict__ A, const int* __restrict__ B,
                       const float* __restrict__ w, float* out_pi, float* out_mu) {
    int tid = threadIdx.x;
    if (blockIdx.x == 0) {
        __shared__ float red[256];
        float v = (tid < NS) ? pi[tid] : -INFINITY;
        red[tid] = v; __syncthreads();
        for (int off = 128; off >= 1; off >>= 1) {
            if (tid < off) red[tid] = fmaxf(red[tid], red[tid + off]);
            __syncthreads();
        }
        float mx = red[0]; __syncthreads();
        float e = (tid < NS) ? expf(v - mx) : 0.0f;
        red[tid] = e; __syncthreads();
        for (int off = 128; off >= 1; off >>= 1) {
            if (tid < off) red[tid] += red[tid + off];
            __syncthreads();
        }
        float ssum = red[0];
        if (tid < NS) {
            float ps = e / ssum;
            if (out_pi) out_pi[tid] = ps;
            g_logpi[tid] = logf(ps + 1e-30f);
        }
        if (out_mu) {
            for (int i = tid; i < DLAT * NK; i += blockDim.x) out_mu[i] = mu[i];
        }
    } else {
        int s = blockIdx.x - 1;
        __shared__ float r0[256], r1[256], r2[256];
        __shared__ float gam_sh;
        int ia = A[s], ib = B[s];
        float vb = 0.0f, dv = 0.0f;
        if (tid < DLAT) {
            float va = mu[tid * NK + ia];
            vb = mu[tid * NK + ib];
            dv = va - vb;
        }
        r0[tid] = vb * vb; r1[tid] = vb * dv; r2[tid] = dv * dv;
        __syncthreads();
        for (int off = 128; off >= 1; off >>= 1) {
            if (tid < off) {
                r0[tid] += r0[tid + off];
                r1[tid] += r1[tid + off];
                r2[tid] += r2[tid + off];
            }
            __syncthreads();
        }
        if (tid == 0) {
            g_bb[s] = r0[0];
            g_cb[s] = r1[0];
            gam_sh = -0.5f * r2[0];
        }
        __syncthreads();
        if (tid < MM) {
            float wv = w[tid];
            g_u[s * MM + tid] = expf(gam_sh * wv * wv);
        }
    }
}

// ---------- main: fused small-GEMM + 4-chain Horner + logsumexp ----------
__global__ void __launch_bounds__(THREADS, 2)
k_main(const float* __restrict__ z, const float* __restrict__ mu,
       const int* __restrict__ A, const int* __restrict__ B,
       const float* __restrict__ w, float* __restrict__ out_lp) {
    extern __shared__ float sm[];
    float* su   = sm;                        // NS*MM = 13600
    float* zs   = su + NS * MM;              // ROWS*ZSTRIDE = 4224
    float* ms   = zs + ROWS * ZSTRIDE;       // 128*16 = 2048
    float* sG   = ms + DLAT * NK;            // 32*17 = 544
    float* sz2  = sG + ROWS * 17;            // 32
    float* sac  = sz2 + ROWS;                // 136
    float* scb  = sac + NS;                  // 136
    int*   sA   = (int*)(scb + NS);          // 136
    int*   sB   = sA + NS;                   // 136
    float* psum = (float*)(sB + NS);         // 8*32 = 256

    int tid = threadIdx.x;
    int b0 = blockIdx.x * ROWS;

    // z tile, float4-coalesced from GMEM, bank-skewed rows in SMEM
    const float4* zg = (const float4*)(z + (size_t)b0 * DLAT);
    for (int i = tid; i < ROWS * DLAT / 4; i += THREADS) {
        int rr = i >> 5;          // 32 float4 per row
        int c4 = i & 31;
        float4 v = zg[i];
        float* dst = zs + rr * ZSTRIDE + c4 * 4;
        dst[0] = v.x; dst[1] = v.y; dst[2] = v.z; dst[3] = v.w;
    }
    for (int i = tid; i < DLAT * NK; i += THREADS) ms[i] = mu[i];
    for (int i = tid; i < NS * MM; i += THREADS) su[i] = g_u[i];
    if (tid < NS) {
        sac[tid] = g_logpi[tid] - 0.5f * g_bb[tid];
        scb[tid] = g_cb[tid];
        sA[tid]  = A[tid];
        sB[tid]  = B[tid];
    }
    __syncthreads();

    // fused GEMM: G[r][k] = z[r] . mu[:,k]; 2 rows per thread; z2 alongside
    {
        int k = tid & 15, r0i = tid >> 4;
#pragma unroll
        for (int it = 0; it < 2; it++) {
            int r = r0i + 16 * it;
            const float* zr = zs + r * ZSTRIDE;
            float acc = 0.0f, zz = 0.0f;
#pragma unroll 8
            for (int d4 = 0; d4 < DLAT / 4; d4++) {
                float4 zv = *(const float4*)(zr + d4 * 4);
                int db = d4 * 4;
                acc = fmaf(zv.x, ms[(db + 0) * NK + k], acc);
                acc = fmaf(zv.y, ms[(db + 1) * NK + k], acc);
                acc = fmaf(zv.z, ms[(db + 2) * NK + k], acc);
                acc = fmaf(zv.w, ms[(db + 3) * NK + k], acc);
                if (k == 0) {
                    zz = fmaf(zv.x, zv.x, zz);
                    zz = fmaf(zv.y, zv.y, zz);
                    zz = fmaf(zv.z, zv.z, zz);
                    zz = fmaf(zv.w, zv.w, zz);
                }
            }
            sG[r * 17 + k] = acc;
            if (k == 0) sz2[r] = zz;
        }
    }
    __syncthreads();

    // main loop: each thread owns row r, state group j (warp-uniform states)
    int r = tid & 31;
    int j = tid >> 5;
    float w1 = w[1];
    float acc = 0.0f;
    const float* gr = sG + r * 17;

#pragma unroll 1
    for (int i = 0; i < SPG; i++) {
        int s = j * SPG + i;
        int ia = sA[s], ib = sB[s];
        float gA = gr[ia];
        float gB = gr[ib];
        float beta  = gA - gB - scb[s];
        float alpha = sac[s] + gB;
        float rr  = __expf(beta * w1);
        float rr2 = rr * rr;
        float rr4 = rr2 * rr2;
        const float4* up = (const float4*)(su + s * MM);
        float f0 = 0.0f, f1 = 0.0f, f2 = 0.0f, f3 = 0.0f;
#pragma unroll
        for (int g = MM / 4 - 1; g >= 0; g--) {
            float4 u4 = up[g];
            f0 = fmaf(rr4, f0, u4.x);
            f1 = fmaf(rr4, f1, u4.y);
            f2 = fmaf(rr4, f2, u4.z);
            f3 = fmaf(rr4, f3, u4.w);
        }
        float f = fmaf(rr, f1, f0) + rr2 * fmaf(rr, f3, f2);
        acc = fmaf(__expf(alpha), f, acc);
    }

    psum[j * 32 + r] = acc;
    __syncthreads();
    if (tid < ROWS) {
        float tot = 0.0f;
#pragma unroll
        for (int q = 0; q < NGROUP; q++) tot += psum[q * 32 + tid];
        const float C = -0.5f * (float)DLAT * 1.8378770664093453f;  // -D/2 ln(2pi)
        out_lp[b0 + tid] = C - 0.5f * sz2[tid] - logf((float)MM) + logf(tot);
    }
}

// ---------- launcher ----------
extern "C" void kernel_launch(void* const* d_in, const int* in_sizes, int n_in,
                              void* d_out, int out_size) {
    const float* z  = (const float*)d_in[0];
    const float* mu = (const float*)d_in[1];
    const float* pi = (const float*)d_in[2];
    const float* w  = (const float*)d_in[3];
    const int*   A  = (const int*)d_in[4];
    const int*   B  = (const int*)d_in[5];
    float* out = (float*)d_out;

    float* out_pi = nullptr;
    float* out_mu = nullptr;
    float* out_lp = out;
    if (out_size >= NS + DLAT * NK + NB) {
        out_pi = out;
        out_mu = out + NS;
        out_lp = out + NS + DLAT * NK;
    }

    const int SMEM = (NS * MM + ROWS * ZSTRIDE + DLAT * NK + ROWS * 17 + ROWS
                      + NS + NS + NS + NS + NGROUP * ROWS) * 4;
    cudaFuncSetAttribute(k_main, cudaFuncAttributeMaxDynamicSharedMemorySize, SMEM);

    k_prep<<<1 + NS, 256>>>(pi, mu, A, B, w, out_pi, out_mu);
    k_main<<<NB / ROWS, THREADS, SMEM>>>(z, mu, A, B, w, out_lp);
}

// round 5
// speedup vs baseline: 1.2741x; 1.2741x over previous
#include <cuda_runtime.h>
#include <math.h>

#define NK   16
#define DLAT 128
#define MM   100
#define MP   104            // MM padded to multiple of 8 (zero coeffs)
#define NS   136
#define NB   8192
#define ROWS 64
#define THREADS 1024
#define NGROUP 16           // THREADS / ROWS
#define SPG 9               // ceil(NS / NGROUP); tail guarded (warp-uniform)
#define ZSTRIDE 132

// packed fp32x2 FMA: d = a*b + c (element-wise on 2 floats in a 64-bit reg)
#define FMA2(d, a, b, c) \
    asm("fma.rn.f32x2 %0, %1, %2, %3;" : "=l"(d) : "l"(a), "l"(b), "l"(c))
#define PACK2(d, x) \
    asm("mov.b64 %0, {%1, %1};" : "=l"(d) : "f"(x))
#define UNPACK2(lo, hi, v) \
    asm("mov.b64 {%0, %1}, %2;" : "=f"(lo), "=f"(hi) : "l"(v))

// ---------- device scratch ----------
__device__ float g_logpi[NS];
__device__ float g_bb[NS];        // |muB|^2
__device__ float g_cb[NS];        // muB . (muA - muB)
__device__ float g_u[NS * MP];    // exp(gamma_s * w_m^2), zero-padded m=100..103

// ---------- prep: block 0 = softmax(pi)+outputs; blocks 1..NS = per-state ----------
__global__ void k_prep(const float* __restrict__ pi, const float* __restrict__ mu,
                       const int* __restrict__ A, const int* __restrict__ B,
                       const float* __restrict__ w, float* out_pi, float* out_mu) {
    int tid = threadIdx.x;
    if (blockIdx.x == 0) {
        __shared__ float red[256];
        float v = (tid < NS) ? pi[tid] : -INFINITY;
        red[tid] = v; __syncthreads();
        for (int off = 128; off >= 1; off >>= 1) {
            if (tid < off) red[tid] = fmaxf(red[tid], red[tid + off]);
            __syncthreads();
        }
        float mx = red[0]; __syncthreads();
        float e = (tid < NS) ? expf(v - mx) : 0.0f;
        red[tid] = e; __syncthreads();
        for (int off = 128; off >= 1; off >>= 1) {
            if (tid < off) red[tid] += red[tid + off];
            __syncthreads();
        }
        float ssum = red[0];
        if (tid < NS) {
            float ps = e / ssum;
            if (out_pi) out_pi[tid] = ps;
            g_logpi[tid] = logf(ps + 1e-30f);
        }
        if (out_mu) {
            for (int i = tid; i < DLAT * NK; i += blockDim.x) out_mu[i] = mu[i];
        }
    } else {
        int s = blockIdx.x - 1;
        __shared__ float r0[256], r1[256], r2[256];
        __shared__ float gam_sh;
        int ia = A[s], ib = B[s];
        float vb = 0.0f, dv = 0.0f;
        if (tid < DLAT) {
            float va = mu[tid * NK + ia];
            vb = mu[tid * NK + ib];
            dv = va - vb;
        }
        r0[tid] = vb * vb; r1[tid] = vb * dv; r2[tid] = dv * dv;
        __syncthreads();
        for (int off = 128; off >= 1; off >>= 1) {
            if (tid < off) {
                r0[tid] += r0[tid + off];
                r1[tid] += r1[tid + off];
                r2[tid] += r2[tid + off];
            }
            __syncthreads();
        }
        if (tid == 0) {
            g_bb[s] = r0[0];
            g_cb[s] = r1[0];
            gam_sh = -0.5f * r2[0];
        }
        __syncthreads();
        if (tid < MP) {
            float uval = 0.0f;
            if (tid < MM) {
                float wv = w[tid];
                uval = expf(gam_sh * wv * wv);
            }
            g_u[s * MP + tid] = uval;
        }
    }
}

// ---------- main: fused small-GEMM + 8-chain FFMA2 Horner + logsumexp ----------
__global__ void __launch_bounds__(THREADS, 1)
k_main(const float* __restrict__ z, const float* __restrict__ mu,
       const int* __restrict__ A, const int* __restrict__ B,
       const float* __restrict__ w, float* __restrict__ out_lp) {
    extern __shared__ float sm[];
    float* su   = sm;                        // NS*MP  = 14144
    float* zs   = su + NS * MP;              // 64*132 = 8448
    float* ms   = zs + ROWS * ZSTRIDE;       // 2048
    float* sG   = ms + DLAT * NK;            // 64*17 = 1088
    float* sz2  = sG + ROWS * 17;            // 64
    float* sac  = sz2 + ROWS;                // 136
    float* scb  = sac + NS;                  // 136
    int*   sA   = (int*)(scb + NS);          // 136
    int*   sB   = sA + NS;                   // 136
    float* psum = (float*)(sB + NS);         // 16*64 = 1024

    int tid = threadIdx.x;
    int b0 = blockIdx.x * ROWS;

    // z tile (coalesced float4, bank-skewed rows)
    const float4* zg = (const float4*)(z + (size_t)b0 * DLAT);
    for (int i = tid; i < ROWS * DLAT / 4; i += THREADS) {
        int rr = i >> 5, c4 = i & 31;
        float4 v = zg[i];
        float* dst = zs + rr * ZSTRIDE + c4 * 4;
        dst[0] = v.x; dst[1] = v.y; dst[2] = v.z; dst[3] = v.w;
    }
    for (int i = tid; i < DLAT * NK; i += THREADS) ms[i] = mu[i];
    for (int i = tid; i < NS * MP / 4; i += THREADS)
        ((float4*)su)[i] = ((const float4*)g_u)[i];
    if (tid < NS) {
        sac[tid] = g_logpi[tid] - 0.5f * g_bb[tid];
        scb[tid] = g_cb[tid];
        sA[tid]  = A[tid];
        sB[tid]  = B[tid];
    }
    __syncthreads();

    // fused GEMM: one (row, k) per thread; z2 alongside for k==0
    {
        int k = tid & 15, r = tid >> 4;      // r in 0..63
        const float* zr = zs + r * ZSTRIDE;
        float acc = 0.0f, zz = 0.0f;
#pragma unroll 8
        for (int d4 = 0; d4 < DLAT / 4; d4++) {
            float4 zv = *(const float4*)(zr + d4 * 4);
            int db = d4 * 4;
            acc = fmaf(zv.x, ms[(db + 0) * NK + k], acc);
            acc = fmaf(zv.y, ms[(db + 1) * NK + k], acc);
            acc = fmaf(zv.z, ms[(db + 2) * NK + k], acc);
            acc = fmaf(zv.w, ms[(db + 3) * NK + k], acc);
            if (k == 0) {
                zz = fmaf(zv.x, zv.x, zz);
                zz = fmaf(zv.y, zv.y, zz);
                zz = fmaf(zv.z, zv.z, zz);
                zz = fmaf(zv.w, zv.w, zz);
            }
        }
        sG[r * 17 + k] = acc;
        if (k == 0) sz2[r] = zz;
    }
    __syncthreads();

    // main loop: thread owns row r; 16 warp-uniform state groups
    int r = tid & 63;
    int j = tid >> 6;                        // 0..15, warp-uniform
    float w1 = w[1];
    float acc = 0.0f;
    const float* gr = sG + r * 17;

#pragma unroll 1
    for (int i = 0; i < SPG; i++) {
        int s = j * SPG + i;
        if (s >= NS) break;                  // warp-uniform exit
        int ia = sA[s], ib = sB[s];
        float gA = gr[ia];
        float gB = gr[ib];
        float beta  = gA - gB - scb[s];
        float alpha = sac[s] + gB;
        float rr1 = __expf(beta * w1);
        float rr2 = rr1 * rr1;
        float rr4 = rr2 * rr2;
        float rr8 = rr4 * rr4;
        unsigned long long rr8p;
        PACK2(rr8p, rr8);

        const ulonglong2* up = (const ulonglong2*)(su + s * MP);
        unsigned long long F01 = 0ull, F23 = 0ull, F45 = 0ull, F67 = 0ull;
#pragma unroll
        for (int g = MP / 8 - 1; g >= 0; g--) {
            ulonglong2 ua = up[2 * g];       // u[8g+0..3] as 2 packed pairs
            ulonglong2 ub = up[2 * g + 1];   // u[8g+4..7]
            FMA2(F01, rr8p, F01, ua.x);
            FMA2(F23, rr8p, F23, ua.y);
            FMA2(F45, rr8p, F45, ub.x);
            FMA2(F67, rr8p, F67, ub.y);
        }
        float f0, f1, f2, f3, f4, f5, f6, f7;
        UNPACK2(f0, f1, F01);
        UNPACK2(f2, f3, F23);
        UNPACK2(f4, f5, F45);
        UNPACK2(f6, f7, F67);
        float fa = fmaf(rr1, f1, f0);
        float fb = fmaf(rr1, f3, f2);
        float fc = fmaf(rr1, f5, f4);
        float fd = fmaf(rr1, f7, f6);
        float f  = fmaf(rr2, fb, fa) + rr4 * fmaf(rr2, fd, fc);
        acc = fmaf(__expf(alpha), f, acc);
    }

    psum[j * 64 + r] = acc;
    __syncthreads();
    if (tid < ROWS) {
        float tot = 0.0f;
#pragma unroll
        for (int q = 0; q < NGROUP; q++) tot += psum[q * 64 + tid];
        const float C = -0.5f * (float)DLAT * 1.8378770664093453f;  // -D/2 ln(2pi)
        out_lp[b0 + tid] = C - 0.5f * sz2[tid] - logf((float)MM) + logf(tot);
    }
}

// ---------- launcher ----------
extern "C" void kernel_launch(void* const* d_in, const int* in_sizes, int n_in,
                              void* d_out, int out_size) {
    const float* z  = (const float*)d_in[0];
    const float* mu = (const float*)d_in[1];
    const float* pi = (const float*)d_in[2];
    const float* w  = (const float*)d_in[3];
    const int*   A  = (const int*)d_in[4];
    const int*   B  = (const int*)d_in[5];
    float* out = (float*)d_out;

    float* out_pi = nullptr;
    float* out_mu = nullptr;
    float* out_lp = out;
    if (out_size >= NS + DLAT * NK + NB) {
        out_pi = out;
        out_mu = out + NS;
        out_lp = out + NS + DLAT * NK;
    }

    const int SMEM = (NS * MP + ROWS * ZSTRIDE + DLAT * NK + ROWS * 17 + ROWS
                      + NS * 4 + NGROUP * ROWS) * 4;
    cudaFuncSetAttribute(k_main, cudaFuncAttributeMaxDynamicSharedMemorySize, SMEM);

    k_prep<<<1 + NS, 256>>>(pi, mu, A, B, w, out_pi, out_mu);
    k_main<<<NB / ROWS, THREADS, SMEM>>>(z, mu, A, B, w, out_lp);
}

// round 6
// speedup vs baseline: 1.4100x; 1.1067x over previous
#include <cuda_runtime.h>
#include <math.h>

#define NK   16
#define DLAT 128
#define MM   100
#define MP   104            // MM padded to multiple of 8 (zero coeffs)
#define NS   136
#define NB   8192
#define ROWS 64
#define THREADS 1024
#define NWARP 32            // warps per CTA = state groups
#define ZSTRIDE 132

typedef unsigned long long ull;

#define FMA2(d, a, b, c) \
    asm("fma.rn.f32x2 %0, %1, %2, %3;" : "=l"(d) : "l"(a), "l"(b), "l"(c))
#define PACK2(d, x) \
    asm("mov.b64 %0, {%1, %1};" : "=l"(d) : "f"(x))
#define UNPACK2(lo, hi, v) \
    asm("mov.b64 {%0, %1}, %2;" : "=f"(lo), "=f"(hi) : "l"(v))

// ---------- device scratch ----------
__device__ float g_logpi[NS];
__device__ float g_bb[NS];        // |muB|^2
__device__ float g_cb[NS];        // muB . (muA - muB)
__device__ float g_u[NS * MP];    // exp(gamma_s * w_m^2), zero-padded

// ---------- prep ----------
__global__ void k_prep(const float* __restrict__ pi, const float* __restrict__ mu,
                       const int* __restrict__ A, const int* __restrict__ B,
                       const float* __restrict__ w, float* out_pi, float* out_mu) {
    int tid = threadIdx.x;
    if (blockIdx.x == 0) {
        __shared__ float red[256];
        float v = (tid < NS) ? pi[tid] : -INFINITY;
        red[tid] = v; __syncthreads();
        for (int off = 128; off >= 1; off >>= 1) {
            if (tid < off) red[tid] = fmaxf(red[tid], red[tid + off]);
            __syncthreads();
        }
        float mx = red[0]; __syncthreads();
        float e = (tid < NS) ? expf(v - mx) : 0.0f;
        red[tid] = e; __syncthreads();
        for (int off = 128; off >= 1; off >>= 1) {
            if (tid < off) red[tid] += red[tid + off];
            __syncthreads();
        }
        float ssum = red[0];
        if (tid < NS) {
            float ps = e / ssum;
            if (out_pi) out_pi[tid] = ps;
            g_logpi[tid] = logf(ps + 1e-30f);
        }
        if (out_mu) {
            for (int i = tid; i < DLAT * NK; i += blockDim.x) out_mu[i] = mu[i];
        }
    } else {
        int s = blockIdx.x - 1;
        __shared__ float r0[256], r1[256], r2[256];
        __shared__ float gam_sh;
        int ia = A[s], ib = B[s];
        float vb = 0.0f, dv = 0.0f;
        if (tid < DLAT) {
            float va = mu[tid * NK + ia];
            vb = mu[tid * NK + ib];
            dv = va - vb;
        }
        r0[tid] = vb * vb; r1[tid] = vb * dv; r2[tid] = dv * dv;
        __syncthreads();
        for (int off = 128; off >= 1; off >>= 1) {
            if (tid < off) {
                r0[tid] += r0[tid + off];
                r1[tid] += r1[tid + off];
                r2[tid] += r2[tid + off];
            }
            __syncthreads();
        }
        if (tid == 0) {
            g_bb[s] = r0[0];
            g_cb[s] = r1[0];
            gam_sh = -0.5f * r2[0];
        }
        __syncthreads();
        if (tid < MP) {
            float uval = 0.0f;
            if (tid < MM) {
                float wv = w[tid];
                uval = expf(gam_sh * wv * wv);
            }
            g_u[s * MP + tid] = uval;
        }
    }
}

// ---------- main ----------
__global__ void __launch_bounds__(THREADS, 1)
k_main(const float* __restrict__ z, const float* __restrict__ mu,
       const int* __restrict__ A, const int* __restrict__ B,
       const float* __restrict__ w, float* __restrict__ out_lp) {
    extern __shared__ float sm[];
    float* su   = sm;                        // 14144
    float* zs   = su + NS * MP;              // 8448
    float* msps = zs + ROWS * ZSTRIDE;       // 2048 (ms during GEMM, psum after)
    float* sG   = msps + 2048;               // 64*17 = 1088
    float* sz2  = sG + ROWS * 17;            // 64
    float* sPf  = sz2 + ROWS;                // NS*4 = 544 (packed params)

    int tid = threadIdx.x;
    int b0 = blockIdx.x * ROWS;

    // loads
    const float4* zg = (const float4*)(z + (size_t)b0 * DLAT);
    for (int i = tid; i < ROWS * DLAT / 4; i += THREADS) {
        int rr = i >> 5, c4 = i & 31;
        float4 v = zg[i];
        float* dst = zs + rr * ZSTRIDE + c4 * 4;
        dst[0] = v.x; dst[1] = v.y; dst[2] = v.z; dst[3] = v.w;
    }
    for (int i = tid; i < DLAT * NK; i += THREADS) msps[i] = mu[i];
    for (int i = tid; i < NS * MP / 4; i += THREADS)
        ((float4*)su)[i] = ((const float4*)g_u)[i];
    if (tid < NS) {
        sPf[4 * tid + 0] = g_logpi[tid] - 0.5f * g_bb[tid];
        sPf[4 * tid + 1] = g_cb[tid];
        sPf[4 * tid + 2] = __int_as_float(A[tid]);
        sPf[4 * tid + 3] = __int_as_float(B[tid]);
    }
    __syncthreads();

    // fused GEMM: one (row, k) per thread
    {
        int k = tid & 15, r = tid >> 4;
        const float* zr = zs + r * ZSTRIDE;
        float acc = 0.0f, zz = 0.0f;
#pragma unroll 8
        for (int d4 = 0; d4 < DLAT / 4; d4++) {
            float4 zv = *(const float4*)(zr + d4 * 4);
            int db = d4 * 4;
            acc = fmaf(zv.x, msps[(db + 0) * NK + k], acc);
            acc = fmaf(zv.y, msps[(db + 1) * NK + k], acc);
            acc = fmaf(zv.z, msps[(db + 2) * NK + k], acc);
            acc = fmaf(zv.w, msps[(db + 3) * NK + k], acc);
            if (k == 0) {
                zz = fmaf(zv.x, zv.x, zz);
                zz = fmaf(zv.y, zv.y, zz);
                zz = fmaf(zv.z, zv.z, zz);
                zz = fmaf(zv.w, zv.w, zz);
            }
        }
        sG[r * 17 + k] = acc;
        if (k == 0) sz2[r] = zz;
    }
    __syncthreads();   // also fences msps reuse as psum

    // main loop: warp = state group j; each thread handles rows r and r+32
    int r = tid & 31;
    int j = tid >> 5;                        // warp id, 0..31
    float w1 = w[1];
    const float* gra = sG + r * 17;
    const float* grb = sG + (r + 32) * 17;
    const float4* sP4 = (const float4*)sPf;
    int cnt = (j < 8) ? 5 : 4;               // 8*5 + 24*4 = 136
    float acc_a = 0.0f, acc_b = 0.0f;

    int s = j;
    float4 P = sP4[s];
    int ia = __float_as_int(P.z), ib = __float_as_int(P.w);
    float gAa = gra[ia], gBa = gra[ib];
    float gAb = grb[ia], gBb = grb[ib];

#pragma unroll 1
    for (int i = 0; i < cnt; i++) {
        float beta_a  = gAa - gBa - P.y;
        float alpha_a = P.x + gBa;
        float beta_b  = gAb - gBb - P.y;
        float alpha_b = P.x + gBb;
        float r1a = __expf(beta_a * w1);
        float r1b = __expf(beta_b * w1);
        float r2a = r1a * r1a, r4a = r2a * r2a;
        float r2b = r1b * r1b, r4b = r2b * r2b;
        ull r4ap, r4bp;
        PACK2(r4ap, r4a);
        PACK2(r4bp, r4b);
        const ulonglong2* up = (const ulonglong2*)(su + s * MP);

        // prefetch next state's params + G values (clamped, warp-uniform)
        int sn = s + NWARP;
        int sc = (sn < NS) ? sn : s;
        float4 Pn = sP4[sc];
        int ian = __float_as_int(Pn.z), ibn = __float_as_int(Pn.w);
        float gAan = gra[ian], gBan = gra[ibn];
        float gAbn = grb[ian], gBbn = grb[ibn];

        ull Fa01 = 0ull, Fa23 = 0ull, Fb01 = 0ull, Fb23 = 0ull;
#pragma unroll
        for (int g = MP / 4 - 1; g >= 0; g--) {
            ulonglong2 uu = up[g];           // (u[4g],u[4g+1]) , (u[4g+2],u[4g+3])
            FMA2(Fa01, r4ap, Fa01, uu.x);
            FMA2(Fa23, r4ap, Fa23, uu.y);
            FMA2(Fb01, r4bp, Fb01, uu.x);
            FMA2(Fb23, r4bp, Fb23, uu.y);
        }
        float S0a, S1a, S2a, S3a, S0b, S1b, S2b, S3b;
        UNPACK2(S0a, S1a, Fa01);
        UNPACK2(S2a, S3a, Fa23);
        UNPACK2(S0b, S1b, Fb01);
        UNPACK2(S2b, S3b, Fb23);
        float fa = fmaf(r1a, S1a, S0a) + r2a * fmaf(r1a, S3a, S2a);
        float fb = fmaf(r1b, S1b, S0b) + r2b * fmaf(r1b, S3b, S2b);
        acc_a = fmaf(__expf(alpha_a), fa, acc_a);
        acc_b = fmaf(__expf(alpha_b), fb, acc_b);

        P = Pn; s = sn;
        gAa = gAan; gBa = gBan; gAb = gAbn; gBb = gBbn;
    }

    float* psum = msps;                      // reuse
    psum[j * 64 + r]      = acc_a;
    psum[j * 64 + r + 32] = acc_b;
    __syncthreads();
    if (tid < ROWS) {
        float tot = 0.0f;
#pragma unroll
        for (int q = 0; q < NWARP; q++) tot += psum[q * 64 + tid];
        const float C = -0.5f * (float)DLAT * 1.8378770664093453f;  // -D/2 ln(2pi)
        out_lp[b0 + tid] = C - 0.5f * sz2[tid] - logf((float)MM) + logf(tot);
    }
}

// ---------- launcher ----------
extern "C" void kernel_launch(void* const* d_in, const int* in_sizes, int n_in,
                              void* d_out, int out_size) {
    const float* z  = (const float*)d_in[0];
    const float* mu = (const float*)d_in[1];
    const float* pi = (const float*)d_in[2];
    const float* w  = (const float*)d_in[3];
    const int*   A  = (const int*)d_in[4];
    const int*   B  = (const int*)d_in[5];
    float* out = (float*)d_out;

    float* out_pi = nullptr;
    float* out_mu = nullptr;
    float* out_lp = out;
    if (out_size >= NS + DLAT * NK + NB) {
        out_pi = out;
        out_mu = out + NS;
        out_lp = out + NS + DLAT * NK;
    }

    const int SMEM = (NS * MP + ROWS * ZSTRIDE + 2048 + ROWS * 17 + ROWS + NS * 4) * 4;
    cudaFuncSetAttribute(k_main, cudaFuncAttributeMaxDynamicSharedMemorySize, SMEM);

    k_prep<<<1 + NS, 256>>>(pi, mu, A, B, w, out_pi, out_mu);
    k_main<<<NB / ROWS, THREADS, SMEM>>>(z, mu, A, B, w, out_lp);
}